// round 15
// baseline (speedup 1.0000x reference)
#include <cuda_runtime.h>
#include <cstdint>
#include <cstddef>

#define BATCH   16384
#define DIM     64
#define NSTEPS  100
#define BPC     12                 // samples per CTA
#define TPB     768                // BPC * DIM threads
#define NPAIRS  2016               // upper-triangle pairs of 64x64
#define MROWF   68                 // padded M row (floats): conflict-free LDS.128
#define SSTR    4356               // per-sample M stride: 64*68 + 4 skew (sh-halves on distinct banks)
#define NGROUP  ((BATCH + BPC - 1) / BPC)   // 1366 CTAs
#define NGRP    336                // pair groups (6 pairs each)
#define G3_TOT  (96 * NGRP)        // float4 slots: 6 chunks * 16 kq * 336 groups

typedef unsigned long long ull;

__device__ int g_idx[BATCH];
__device__ int g_perm[BATCH];
__device__ int g_pairs[NPAIRS];
__device__ __align__(16) float4 g_G3[G3_TOT];   // [(c*16+kq)][g]: 16 consecutive g = 256B/warp

// ---------------- packed f32x2 helpers (sm_103a) ----------------
__device__ __forceinline__ ull pack2(float x, float y) {
    ull r; asm("mov.b64 %0, {%1, %2};" : "=l"(r) : "f"(x), "f"(y)); return r;
}
__device__ __forceinline__ void unpack2(ull v, float& x, float& y) {
    asm("mov.b64 {%0, %1}, %2;" : "=f"(x), "=f"(y) : "l"(v));
}
__device__ __forceinline__ ull ffma2(ull a, ull b, ull c) {
    ull d; asm("fma.rn.f32x2 %0, %1, %2, %3;" : "=l"(d) : "l"(a), "l"(b), "l"(c));
    return d;
}
__device__ __forceinline__ void group_bar(int b) {      // 64-thread named barrier
    asm volatile("bar.sync %0, 64;" :: "r"(b + 1) : "memory");
}

// ---------------- setup: idx + descending counting sort + pair table + G planes ----
__global__ void setup_kernel(const float* __restrict__ t, const float* __restrict__ G) {
    __shared__ int hist[NSTEPS];
    __shared__ int off[NSTEPS];
    const int tid = threadIdx.x;                   // 512 threads
    if (tid < NSTEPS) hist[tid] = 0;
    __syncthreads();
    for (int b = tid; b < BATCH; b += blockDim.x) {
        int ix = (int)truncf(100.0f * t[b]);       // trunc(n*t/T), T=1
        ix = min(max(ix, 0), NSTEPS - 1);
        g_idx[b] = ix;
        atomicAdd(&hist[ix], 1);
    }
    if (tid == 0) {                                // diagonal-major pair table
        int p = 0;
        for (int d = 1; d < DIM; ++d)
            for (int i = 0; i + d < DIM; ++i)
                g_pairs[p++] = (i << 8) | (i + d);
    }
    __syncthreads();
    if (tid == 0) {                                // descending bins: long jobs first
        int run = 0;
        for (int bin = NSTEPS - 1; bin >= 0; --bin) { off[bin] = run; run += hist[bin]; }
    }
    __syncthreads();
    for (int b = tid; b < BATCH; b += blockDim.x) {
        int pos = atomicAdd(&off[g_idx[b]], 1);
        g_perm[pos] = b;
    }
    // ---- G planes: slot = (c*16 + kq)*NGRP + g ; pair p = c*NGRP + g ----
    for (int slot = tid; slot < G3_TOT; slot += blockDim.x) {
        int g   = slot % NGRP;
        int ckq = slot / NGRP;
        int kq  = ckq & 15;
        int c   = ckq >> 4;                        // 0..5
        int p   = c * NGRP + g;                    // < 2016 always
        int pr  = g_pairs[p];
        int i = pr >> 8, j = pr & 255;
        g_G3[slot] = *reinterpret_cast<const float4*>(G + ((i * DIM + j) * DIM + 4 * kq));
    }
}

// ---------------- full-register 64-dot (unchanged from R13) ----------------
__device__ __forceinline__ float dot64r(const ulonglong2 (&M)[16],
                                        const ulonglong2* __restrict__ V8) {
    ull a0 = 0ull, a1 = 0ull;
    #pragma unroll
    for (int q = 0; q < 16; ++q) {
        ulonglong2 v = V8[q];                    // broadcast within b-group
        a0 = ffma2(M[q].x, v.x, a0);
        a1 = ffma2(M[q].y, v.y, a1);
    }
    float x0, x1, z0, z1;
    unpack2(a0, x0, x1);
    unpack2(a1, z0, z1);
    return (x0 + x1) + (z0 + z1);
}

// ---------------- main integration kernel ----------------
__global__ void __launch_bounds__(TPB)
sde_kernel(const float* __restrict__ y0,
           const float* __restrict__ dW,
           float* __restrict__ out)
{
    extern __shared__ __align__(16) float smem[];
    float* Msm  = smem;                        // [BPC samples][SSTR]
    float* vbuf = smem + BPC * SSTR;           // ping-pong [2][TPB]
    float* dw3  = vbuf + 2 * TPB;              // [2 sh][388]: per sh, [kq][kk][pos] 16*24 floats

    const int tid = threadIdx.x;
    const int b   = tid >> 6;                  // dot-phase sample
    const int i   = tid & 63;                  // dot-phase row
    const int g   = tid >> 1;                  // mform pair-group (0..335 for tid<672)
    const int sh  = tid & 1;                   // mform sample half

    int gidx = blockIdx.x * BPC + b;
    if (gidx >= BATCH) gidx = BATCH - 1;       // ghost -> duplicate last sample (benign)
    const int sb    = g_perm[gidx];
    const int myidx = g_idx[sb];
    const int smax  = g_idx[g_perm[blockIdx.x * BPC]];   // sorted desc -> first is max

    const bool mf = (tid < 672);
    int prc[6];                                // packed (ii,jj) for my 6 pairs
    #pragma unroll
    for (int c = 0; c < 6; ++c)
        prc[c] = g_pairs[min(c * NGRP + g, NPAIRS - 1)];

    Msm[b * SSTR + i * MROWF + i] = 0.0f;      // diagonal exactly 0, set once

    float yr   = y0[sb * DIM + i];
    float r_dw = dW[(size_t)sb * DIM + i];     // dw(0)

    const ulonglong2* Mr = reinterpret_cast<const ulonglong2*>(Msm + b * SSTR + i * MROWF);
    const ulonglong2* V0 = reinterpret_cast<const ulonglong2*>(vbuf + b * DIM);
    const ulonglong2* V1 = reinterpret_cast<const ulonglong2*>(vbuf + TPB + b * DIM);
    const float* dwb = dw3 + sh * 388;         // my sample-half's dw block
    // staging slot for thread (b,i): sh=b/6, pos=b%6, kq=i>>2, kk=i&3
    const int stg = (b / 6) * 388 + (i >> 2) * 24 + (i & 3) * 6 + (b % 6);

    for (int s = 0; s <= smax; ++s) {
        dw3[stg]  = r_dw;                      // stage dw(s) in mform-ready layout
        vbuf[tid] = yr;                        // v0 = y
        __syncthreads();                       // barA: dw3/v0 ready; prior reads done

        r_dw = dW[((size_t)min(s + 1, NSTEPS - 1) * BATCH + sb) * DIM + i];  // prefetch

        if (mf) {
            // ---- M formation: 6 pairs x 6 samples per thread ----
            ull acc[6][3];
            #pragma unroll
            for (int c = 0; c < 6; ++c)
                #pragma unroll
                for (int q = 0; q < 3; ++q) acc[c][q] = 0ull;

            #pragma unroll 4
            for (int kq = 0; kq < 16; ++kq) {
                ulonglong2 du2[6];             // 24 floats: [kk][3 sample-pairs]
                const ulonglong2* dp =
                    reinterpret_cast<const ulonglong2*>(dwb + kq * 24);
                #pragma unroll
                for (int j = 0; j < 6; ++j) du2[j] = dp[j];
                const ull* du = reinterpret_cast<const ull*>(du2);   // du[kk*3+pp]
                const float4* gq = g_G3 + (size_t)kq * NGRP + g;
                #pragma unroll
                for (int c = 0; c < 6; ++c) {
                    float4 g4 = __ldg(gq + (size_t)c * (16 * NGRP));
                    #pragma unroll
                    for (int kk = 0; kk < 4; ++kk) {
                        float gv = (kk == 0) ? g4.x : (kk == 1) ? g4.y
                                 : (kk == 2) ? g4.z : g4.w;
                        ull gg = pack2(gv, gv);
                        acc[c][0] = ffma2(gg, du[kk * 3 + 0], acc[c][0]);
                        acc[c][1] = ffma2(gg, du[kk * 3 + 1], acc[c][1]);
                        acc[c][2] = ffma2(gg, du[kk * 3 + 2], acc[c][2]);
                    }
                }
            }

            // ---- write both triangles (skew exact) for my 6 samples ----
            float* Mb = Msm + sh * 6 * SSTR;
            #pragma unroll
            for (int c = 0; c < 6; ++c) {
                int ii = prc[c] >> 8, jj = prc[c] & 255;
                float* up = Mb + ii * MROWF + jj;
                float* lo = Mb + jj * MROWF + ii;
                #pragma unroll
                for (int q = 0; q < 3; ++q) {
                    float va, vb;
                    unpack2(acc[c][q], va, vb);
                    up[(2 * q + 0) * SSTR] =  va;  lo[(2 * q + 0) * SSTR] = -va;
                    up[(2 * q + 1) * SSTR] =  vb;  lo[(2 * q + 1) * SSTR] = -vb;
                }
            }
        }
        __syncthreads();                       // barB: M(s) complete & visible

        // Entire M row into registers (16 conflict-free LDS.128).
        ulonglong2 Mrow[16];
        #pragma unroll
        for (int q = 0; q < 16; ++q) Mrow[q] = Mr[q];

        // ---- RK4 stages; per-sample 64-thread named barriers ----
        float u1 = dot64r(Mrow, V0);
        vbuf[TPB + tid] = yr + 0.5f * u1;
        group_bar(b);

        float u2 = dot64r(Mrow, V1);
        vbuf[tid] = yr + 0.5f * u2;
        group_bar(b);

        float u3 = dot64r(Mrow, V0);
        vbuf[TPB + tid] = yr + u3;
        group_bar(b);

        float u4 = dot64r(Mrow, V1);
        yr += (u1 + 2.0f * u2 + 2.0f * u3 + u4) / 6.0f;

        if (s == myidx) out[sb * DIM + i] = yr;            // fused ys[idx_b] gather
        // loop-top barA covers WAR on dw3/vbuf/Msm for next step
    }
}

// ---------------- launch ----------------
extern "C" void kernel_launch(void* const* d_in, const int* in_sizes, int n_in,
                              void* d_out, int out_size) {
    const float* y0 = nullptr;
    const float* t  = nullptr;
    const float* G  = nullptr;
    const float* dW = nullptr;
    for (int k = 0; k < n_in; ++k) {           // robust size-based remap
        const float* p = (const float*)d_in[k];
        long sz = in_sizes[k];
        if      (sz == BATCH)                      t  = p;
        else if (sz == BATCH * DIM)                y0 = p;
        else if (sz == DIM * DIM * DIM)            G  = p;
        else if (sz == (long)NSTEPS * BATCH * DIM) dW = p;
    }
    float* out = (float*)d_out;

    const size_t smem_bytes =
        (size_t)(BPC * SSTR + 2 * TPB + 2 * 388) * sizeof(float);   // 218,336 B
    cudaFuncSetAttribute(sde_kernel, cudaFuncAttributeMaxDynamicSharedMemorySize,
                         (int)smem_bytes);

    setup_kernel<<<1, 512>>>(t, G);
    sde_kernel<<<NGROUP, TPB, smem_bytes>>>(y0, dW, out);
}